// round 14
// baseline (speedup 1.0000x reference)
#include <cuda_runtime.h>

#define D_DIM 1024
#define L_DIM 24
#define TPB   256
#define NW    8            // warps per CTA; each warp owns one row per group
#define CPT   4            // decode: columns per thread (1024/256)
#define EPSV  1e-8f
#define FULL  0xffffffffu

// dynamic shared (floats):
//   sWe [24*1024] | sProj[8*32] | sCor[8*32] | sE2[2][8] | sOss[2][8*8]
#define SM_WE     0
#define SM_PROJ   (L_DIM * D_DIM)
#define SM_CORR   (SM_PROJ + NW * 32)
#define SM_E2     (SM_CORR + NW * 32)
#define SM_OSS    (SM_E2 + 2 * NW)
#define SM_FLOATS (SM_OSS + 2 * NW * NW)
#define SM_BYTES  (SM_FLOATS * 4)

// value-split butterfly: reduces acc[24] (each lane holds partials for all 24
// values) to per-value sums scattered across lanes by the static vid map;
// xor-pairwise tree (deterministic).
#define SPLIT_BUTTERFLY(acc, fin)                                          \
    {                                                                      \
        float w12[12];                                                     \
        _Pragma("unroll")                                                  \
        for (int i = 0; i < 12; ++i) {                                     \
            float don = (lane & 16) ? acc[i] : acc[i + 12];                \
            float rec = __shfl_xor_sync(FULL, don, 16);                    \
            w12[i] = ((lane & 16) ? acc[i + 12] : acc[i]) + rec;           \
        }                                                                  \
        float w6[6];                                                       \
        _Pragma("unroll")                                                  \
        for (int i = 0; i < 6; ++i) {                                      \
            float don = (lane & 8) ? w12[i] : w12[i + 6];                  \
            float rec = __shfl_xor_sync(FULL, don, 8);                     \
            w6[i] = ((lane & 8) ? w12[i + 6] : w12[i]) + rec;              \
        }                                                                  \
        float w3[3];                                                       \
        _Pragma("unroll")                                                  \
        for (int i = 0; i < 3; ++i) {                                      \
            float don = (lane & 4) ? w6[i] : w6[i + 3];                    \
            float rec = __shfl_xor_sync(FULL, don, 4);                     \
            w3[i] = ((lane & 4) ? w6[i + 3] : w6[i]) + rec;                \
        }                                                                  \
        float don4 = (lane & 2) ? w3[0] : w3[2];                           \
        float rec4 = __shfl_xor_sync(FULL, don4, 2);                       \
        float n0 = ((lane & 2) ? w3[2] : w3[0]) + rec4;                    \
        float n1 = w3[1] + __shfl_xor_sync(FULL, w3[1], 2);                \
        float don5 = (lane & 1) ? n0 : n1;                                 \
        float rec5 = __shfl_xor_sync(FULL, don5, 1);                       \
        fin = ((lane & 1) ? n1 : n0) + rec5;                               \
    }

__global__ __launch_bounds__(TPB, 1)
void leech_fused_kernel(const float* __restrict__ data,
                        const float* __restrict__ W_enc,
                        const float* __restrict__ b_enc,
                        const float* __restrict__ W_dec,
                        const float* __restrict__ b_dec,
                        const float* __restrict__ ecs_p,
                        const float* __restrict__ ep_p,
                        float* __restrict__ out,
                        int n_rows)
{
    extern __shared__ float smem[];
    float* sWe   = smem + SM_WE;
    float* sProj = smem + SM_PROJ;
    float* sCor  = smem + SM_CORR;
    float* sE2   = smem + SM_E2;
    float* sOss  = smem + SM_OSS;

    const int t    = threadIdx.x;
    const int wid  = t >> 5;
    const int lane = t & 31;
    const int c0   = t * CPT;          // decode column base

    // ---- prologue: W_enc -> shared, W_dec -> regs ----
    {
        const float4* src = reinterpret_cast<const float4*>(W_enc);
        float4* dst = reinterpret_cast<float4*>(sWe);
        #pragma unroll
        for (int i = 0; i < (L_DIM * D_DIM / 4) / TPB; ++i)
            dst[i * TPB + t] = src[i * TPB + t];
    }
    float wd[CPT][L_DIM];              // W_dec[c0+j][l] — 96 regs
    #pragma unroll
    for (int j = 0; j < CPT; ++j) {
        #pragma unroll
        for (int l = 0; l < L_DIM; l += 4) {
            float4 v = *reinterpret_cast<const float4*>(&W_dec[(c0 + j) * L_DIM + l]);
            wd[j][l + 0] = v.x; wd[j][l + 1] = v.y;
            wd[j][l + 2] = v.z; wd[j][l + 3] = v.w;
        }
    }
    const float4 bd  = *reinterpret_cast<const float4*>(&b_dec[c0]);
    const float  ecs = ecs_p[0];
    const float  ep  = ep_p[0];
    const float  benc = (lane < L_DIM) ? b_enc[lane] : 0.0f;

    // split-butterfly final lane -> value-id map (lanes with (lane&3)==3 hold dups)
    const bool dup = ((lane & 3) == 3);
    const int  vid = 12 * ((lane >> 4) & 1) + 6 * ((lane >> 3) & 1)
                   + 3 * ((lane >> 2) & 1) + ((lane & 2) ? 2 : (lane & 1));

    __syncthreads();

    const int stride  = gridDim.x;
    const int strideG = NW * stride;   // rows advanced per group

    // encode lane columns: chunk c -> col c*128 + lane*4 (coalesced float4)
    const int ecol = lane * 4;

    // initial data load: warp wid owns row row0 + wid*stride
    int row0 = blockIdx.x;
    float4 dd[NW];                     // 8 chunks of this warp's row (32 floats)
    {
        const int rw = row0 + wid * stride;
        #pragma unroll
        for (int c = 0; c < NW; ++c) dd[c] = make_float4(0.f, 0.f, 0.f, 0.f);
        if (rw < n_rows) {
            #pragma unroll
            for (int c = 0; c < NW; ++c)
                dd[c] = *reinterpret_cast<const float4*>(
                            &data[(size_t)rw * D_DIM + c * 128 + ecol]);
        }
    }

    int p = 0;                         // parity for sE2 / sOss

    for (; row0 < n_rows; row0 += strideG) {
        // ================= ENCODE (warp-local, barrier-free) =================
        float acc[L_DIM];
        #pragma unroll
        for (int l = 0; l < L_DIM; ++l) {
            float a = 0.0f;
            #pragma unroll
            for (int c = 0; c < NW; ++c) {
                const float4 w = *reinterpret_cast<const float4*>(
                                     &sWe[l * D_DIM + c * 128 + ecol]);
                a = fmaf(dd[c].x, w.x, a);
                a = fmaf(dd[c].y, w.y, a);
                a = fmaf(dd[c].z, w.z, a);
                a = fmaf(dd[c].w, w.w, a);
            }
            acc[l] = a;
        }
        float ss = 0.0f;
        #pragma unroll
        for (int c = 0; c < NW; ++c) {
            ss = fmaf(dd[c].x, dd[c].x, ss);
            ss = fmaf(dd[c].y, dd[c].y, ss);
            ss = fmaf(dd[c].z, dd[c].z, ss);
            ss = fmaf(dd[c].w, dd[c].w, ss);
        }

        // ---- prefetch next group's row (dd dead from here) ----
        {
            const int rn = row0 + strideG + wid * stride;
            #pragma unroll
            for (int c = 0; c < NW; ++c) dd[c] = make_float4(0.f, 0.f, 0.f, 0.f);
            if (rn < n_rows) {
                #pragma unroll
                for (int c = 0; c < NW; ++c)
                    dd[c] = *reinterpret_cast<const float4*>(
                                &data[(size_t)rn * D_DIM + c * 128 + ecol]);
            }
        }

        // ---- warp-local reductions ----
        float fin;
        SPLIT_BUTTERFLY(acc, fin)
        #pragma unroll
        for (int off = 16; off > 0; off >>= 1)
            ss += __shfl_xor_sync(FULL, ss, off);

        // unscatter proj through warp-private smem strip
        if (!dup) sProj[wid * 32 + vid] = fin;
        __syncwarp();
        const float pr = sProj[wid * 32 + lane];   // proj[lane] for lane<24

        // ---- lattice math: ONLY this warp, for its own row ----
        const float in_e = sqrtf(ss);
        float lp = 0.0f;
        if (lane < L_DIM)
            lp = rintf((pr + benc) / ecs) * ecs;   // exact div + half-even round
        float q = lp * lp;                         // lanes >= 24 contribute 0
        #pragma unroll
        for (int off = 16; off > 0; off >>= 1)
            q += __shfl_xor_sync(FULL, q, off);
        const float out_e = sqrtf(q);

        const float s1  = in_e / (out_e + EPSV) * ep;
        const float lat = lp * s1;
        const float cor = (fabsf(lat) > ecs) ? lat : 0.0f;
        const float in_e2 = fabsf(s1) * out_e;     // ||lattice||

        if (lane < L_DIM) sCor[wid * 32 + lane] = cor;   // single writer per row
        if (lane == 0)    sE2[p * NW + wid] = in_e2;
        __syncthreads();                           // B1: cor/in_e2 visible to all

        // ================= DECODE (CTA-wide, W_dec in regs) =================
        float res[NW][4];
        #pragma unroll
        for (int r = 0; r < NW; ++r) {
            res[r][0] = bd.x; res[r][1] = bd.y;
            res[r][2] = bd.z; res[r][3] = bd.w;
        }
        #pragma unroll
        for (int r = 0; r < NW; ++r) {
            #pragma unroll
            for (int l = 0; l < L_DIM; l += 4) {
                const float4 c4 = *reinterpret_cast<const float4*>(&sCor[r * 32 + l]);
                const float cv[4] = {c4.x, c4.y, c4.z, c4.w};
                #pragma unroll
                for (int k = 0; k < 4; ++k) {
                    res[r][0] = fmaf(cv[k], wd[0][l + k], res[r][0]);
                    res[r][1] = fmaf(cv[k], wd[1][l + k], res[r][1]);
                    res[r][2] = fmaf(cv[k], wd[2][l + k], res[r][2]);
                    res[r][3] = fmaf(cv[k], wd[3][l + k], res[r][3]);
                }
            }
        }

        // ---- out_e2 partials: per-warp butterfly per row (tree == R12) ----
        #pragma unroll
        for (int r = 0; r < NW; ++r) {
            float oss = res[r][0] * res[r][0] + res[r][1] * res[r][1]
                      + res[r][2] * res[r][2] + res[r][3] * res[r][3];
            #pragma unroll
            for (int off = 16; off > 0; off >>= 1)
                oss += __shfl_xor_sync(FULL, oss, off);
            if (lane == 0) sOss[p * (NW * NW) + wid * NW + r] = oss;
        }
        __syncthreads();                           // B2: oss partials visible

        // ---- finalize + store all 8 rows ----
        #pragma unroll
        for (int r = 0; r < NW; ++r) {
            float oe2 = 0.0f;
            #pragma unroll
            for (int w = 0; w < NW; ++w)
                oe2 += sOss[p * (NW * NW) + w * NW + r];
            const float s2 = sE2[p * NW + r] / (sqrtf(oe2) + EPSV) * ep;
            const int rr = row0 + r * stride;
            if (rr < n_rows) {
                float4 o;
                o.x = res[r][0] * s2; o.y = res[r][1] * s2;
                o.z = res[r][2] * s2; o.w = res[r][3] * s2;
                *reinterpret_cast<float4*>(&out[(size_t)rr * D_DIM + c0]) = o;
            }
        }

        p ^= 1;   // parity: sE2/sOss read(i) vs write(i+1) have no barrier between
    }
}

extern "C" void kernel_launch(void* const* d_in, const int* in_sizes, int n_in,
                              void* d_out, int out_size)
{
    const float* data  = (const float*)d_in[0];
    const float* W_enc = (const float*)d_in[1];
    const float* b_enc = (const float*)d_in[2];
    const float* W_dec = (const float*)d_in[3];
    const float* b_dec = (const float*)d_in[4];
    const float* ecs   = (const float*)d_in[5];
    const float* ep    = (const float*)d_in[6];
    float* out = (float*)d_out;

    const int n_rows = in_sizes[0] / D_DIM;   // 32768

    int dev = 0;
    cudaGetDevice(&dev);
    int sms = 0;
    cudaDeviceGetAttribute(&sms, cudaDevAttrMultiProcessorCount, dev);
    if (sms <= 0) sms = 148;

    cudaFuncSetAttribute(leech_fused_kernel,
                         cudaFuncAttributeMaxDynamicSharedMemorySize, SM_BYTES);

    leech_fused_kernel<<<sms, TPB, SM_BYTES>>>(data, W_enc, b_enc, W_dec, b_dec,
                                               ecs, ep, out, n_rows);
}